// round 9
// baseline (speedup 1.0000x reference)
#include <cuda_runtime.h>
#include <cuda_fp16.h>
#include <cstdint>
#include <math.h>

// ===========================================================================
// S2Attention on GB300 (sm_103 portable mma.sync path, fp16 numerics)
//   - q/out 1x1 convs: single-pass fp16 W (q errs enter softmax absolutely;
//     out err budgeted), k/v convs: W hi/lo 2-pass (free: latency-bound)
//   - attention: single-pass fp16 HMMA
// B=8, C=512, H=W=64, HEADS=8, d=64, kv tokens 17x17=289 (pad 296)
// ===========================================================================

#define HWQ  4096
#define NKV  289

// ---------------- device scratch ----------------
__device__ __align__(256) __half g_semT [8L * 4096 * 512];  // [b][tok][512]
__device__ __align__(256) __half g_kpreT[8L * 289 * 512];
__device__ __align__(256) __half g_vpreT[8L * 289 * 512];
__device__ __align__(256) __half g_aoT  [8L * 4096 * 512];
__device__ __align__(256) __half g_qT   [8L * 4096 * 512];  // q*0.125
__device__ __align__(256) __half g_kT   [8L * 289 * 512];
__device__ __align__(256) __half g_vC   [8L * 512 * 296];   // [b][c][296] pad0
__device__ __align__(256) float  g_preK [8L * 289 * 512];   // [b][pos][c]
__device__ __align__(256) float  g_preV [8L * 289 * 512];
__device__ __align__(256) __half g_whi  [3L * 512 * 512];   // 0=wq*0.125,1=wpw,2=wout
__device__ __align__(256) __half g_wlo  [3L * 512 * 512];

// ---------------- helpers ----------------
__device__ __forceinline__ uint32_t smem_u32(const void* p) {
    uint32_t a;
    asm("{ .reg .u64 t; cvta.to.shared.u64 t, %1; cvt.u32.u64 %0, t; }"
        : "=r"(a) : "l"(p));
    return a;
}
__device__ __forceinline__ void mma_f16(float* d, const uint32_t* a, const uint32_t* b) {
    asm volatile(
        "mma.sync.aligned.m16n8k16.row.col.f32.f16.f16.f32 "
        "{%0,%1,%2,%3}, {%4,%5,%6,%7}, {%8,%9}, {%0,%1,%2,%3};"
        : "+f"(d[0]), "+f"(d[1]), "+f"(d[2]), "+f"(d[3])
        : "r"(a[0]), "r"(a[1]), "r"(a[2]), "r"(a[3]), "r"(b[0]), "r"(b[1]));
}
__device__ __forceinline__ void cpa16(uint32_t dst, const void* src, uint32_t nbytes) {
    asm volatile("cp.async.cg.shared.global [%0], [%1], 16, %2;"
                 :: "r"(dst), "l"(src), "r"(nbytes) : "memory");
}
#define CPA_COMMIT() asm volatile("cp.async.commit_group;" ::: "memory")
#define CPA_WAIT0()  asm volatile("cp.async.wait_group 0;" ::: "memory")

__device__ __forceinline__ uint32_t packh(float hi, float lo) {
    uint32_t r;
    asm("cvt.rn.f16x2.f32 %0, %1, %2;" : "=r"(r) : "f"(hi), "f"(lo));
    return r;  // lower half <- lo, upper half <- hi
}

// ---------------------------------------------------------------------------
// prep: weights -> fp16 hi/lo (wq pre-scaled by 0.125)
// ---------------------------------------------------------------------------
__global__ void prep_w(const float* __restrict__ wq, const float* __restrict__ wpw,
                       const float* __restrict__ wout)
{
    int i = blockIdx.x * 256 + threadIdx.x;
    if (i >= 3 * 262144) return;
    int widx = i >> 18, j = i & 262143;
    float v = (widx == 0) ? wq[j] * 0.125f : (widx == 1) ? wpw[j] : wout[j];
    __half h = __float2half_rn(v);
    g_whi[i] = h;
    g_wlo[i] = __float2half_rn(v - __half2float(h));
}

// ---------------------------------------------------------------------------
// transpose: sem [b][c][4096] fp32 -> g_semT fp16 [b][tok][512]
// ---------------------------------------------------------------------------
__global__ __launch_bounds__(256)
void transpose_split(const float* __restrict__ in)
{
    __shared__ float tile[32][33];
    int b = blockIdx.z, n0 = blockIdx.x * 32, c0 = blockIdx.y * 32;
    int tx = threadIdx.x, ty = threadIdx.y;
#pragma unroll
    for (int k = 0; k < 4; k++) {
        int c = c0 + ty + 8 * k;
        tile[ty + 8 * k][tx] = in[((long)b * 512 + c) * 4096 + n0 + tx];
    }
    __syncthreads();
#pragma unroll
    for (int k = 0; k < 4; k++) {
        int n = n0 + ty + 8 * k;
        g_semT[((long)b * 4096 + n) * 512 + c0 + tx] =
            __float2half_rn(tile[tx][ty + 8 * k]);
    }
}

// ---------------------------------------------------------------------------
// depthwise 4x4 s4 p2 conv, coalesced: one block per (c, b, which-input)
// ---------------------------------------------------------------------------
__global__ __launch_bounds__(128)
void dw_kernel(const float* __restrict__ in0, const float* __restrict__ in1,
               const float* __restrict__ wdw)
{
    __shared__ float plane[4096];
    const int c = blockIdx.x, b = blockIdx.y, t = threadIdx.x;
    const float* in = blockIdx.z ? in1 : in0;
    float* outp = blockIdx.z ? g_preV : g_preK;
    const float4* ip = (const float4*)(in + ((long)b * 512 + c) * 4096);
#pragma unroll
    for (int i = t; i < 1024; i += 128) ((float4*)plane)[i] = ip[i];
    float wr[16];
#pragma unroll
    for (int i = 0; i < 16; i++) wr[i] = wdw[c * 16 + i];
    __syncthreads();

    for (int pos = t; pos < 289; pos += 128) {
        int oy = pos / 17, ox = pos - oy * 17;
        float acc = 0.f;
#pragma unroll
        for (int ky = 0; ky < 4; ky++) {
            int y = oy * 4 - 2 + ky;
            if ((unsigned)y < 64u) {
#pragma unroll
                for (int kx = 0; kx < 4; kx++) {
                    int xx = ox * 4 - 2 + kx;
                    if ((unsigned)xx < 64u)
                        acc = fmaf(wr[ky * 4 + kx], plane[y * 64 + xx], acc);
                }
            }
        }
        outp[((long)b * 289 + pos) * 512 + c] = acc;
    }
}

// ---------------------------------------------------------------------------
// channel LayerNorm per token -> token-major fp16. grid (289,8,2), block 512
// ---------------------------------------------------------------------------
__global__ __launch_bounds__(512)
void ln_kernel(const float* __restrict__ lng, const float* __restrict__ lnb)
{
    const float* inp = blockIdx.z ? g_preV : g_preK;
    __half* oh = blockIdx.z ? g_vpreT : g_kpreT;
    const int pos = blockIdx.x, b = blockIdx.y, c = threadIdx.x;
    float acc = inp[((long)b * 289 + pos) * 512 + c];

    __shared__ float s1[16], s2[16];
    float v1 = acc, v2 = acc * acc;
#pragma unroll
    for (int o = 16; o > 0; o >>= 1) {
        v1 += __shfl_xor_sync(0xffffffffu, v1, o);
        v2 += __shfl_xor_sync(0xffffffffu, v2, o);
    }
    int w = threadIdx.x >> 5, lane = threadIdx.x & 31;
    if (lane == 0) { s1[w] = v1; s2[w] = v2; }
    __syncthreads();
    if (w == 0) {
        v1 = (lane < 16) ? s1[lane] : 0.f;
        v2 = (lane < 16) ? s2[lane] : 0.f;
#pragma unroll
        for (int o = 8; o > 0; o >>= 1) {
            v1 += __shfl_xor_sync(0xffffffffu, v1, o);
            v2 += __shfl_xor_sync(0xffffffffu, v2, o);
        }
        if (lane == 0) { s1[0] = v1; s2[0] = v2; }
    }
    __syncthreads();
    float mean = s1[0] * (1.f / 512.f);
    float var  = s2[0] * (1.f / 512.f) - mean * mean;
    float val  = (acc - mean) * rsqrtf(var + 1e-5f) * lng[c] + lnb[c];
    oh[((long)b * 289 + pos) * 512 + c] = __float2half_rn(val);
}

// ---------------------------------------------------------------------------
// HMMA GEMM: Out[b][tok][co] = sum_ci W[co][ci] * A[b][tok][ci]
// passes: 1 = W hi only; 2 = W hi + lo. K-chunks of 32, double-buffered.
// Stages use bytes [0, 61440); fp32 epilogue staging needs 67584 B -> GSM.
// ---------------------------------------------------------------------------
#define GST 30720
#define GSM 67584

__global__ __launch_bounds__(256, 1)
void gemm_mma(int asel, int widx, int osel, int passes,
              float* __restrict__ extOut, int Ntok)
{
    extern __shared__ char sm[];
    const uint32_t smb = smem_u32(sm);
    const int t = threadIdx.x, wid = t >> 5, lane = t & 31;
    const int qr = lane >> 2, qc = lane & 3;
    const int b = blockIdx.z, m0 = blockIdx.y * 128, n0 = blockIdx.x * 128;
    const int wm = wid >> 2, wn = wid & 3;

    const __half* A = (asel == 0) ? g_semT : (asel == 1) ? g_kpreT
                    : (asel == 2) ? g_vpreT : g_aoT;
    A += (long)b * Ntok * 512;
    const __half* Whi = g_whi + (long)widx * 262144;
    const __half* Wlo = g_wlo + (long)widx * 262144;

    float acc[4][4][4];
#pragma unroll
    for (int i = 0; i < 4; i++)
#pragma unroll
        for (int j = 0; j < 4; j++)
#pragma unroll
            for (int k = 0; k < 4; k++) acc[i][j][k] = 0.f;

    auto load_chunk = [&](int c, int stage) {
        const int k0 = c * 32;
        const uint32_t sb = smb + stage * GST;
#pragma unroll
        for (int u = 0; u < 2; u++) {
            int q = t + 256 * u;
            int row = q >> 2, cq = q & 3;
            uint32_t soff = (uint32_t)(row * 80 + cq * 16);
            long wof = ((long)(m0 + row) << 9) + k0 + cq * 8;
            cpa16(sb + soff, Whi + wof, 16u);
            if (passes == 2) cpa16(sb + 10240 + soff, Wlo + wof, 16u);
            int tok = n0 + row;
            uint32_t asz = (tok < Ntok) ? 16u : 0u;
            long aof = ((long)(asz ? tok : 0) << 9) + k0 + cq * 8;
            cpa16(sb + 20480 + soff, A + aof, asz);
        }
        CPA_COMMIT();
    };

    load_chunk(0, 0);

    for (int c = 0; c < 16; c++) {
        CPA_WAIT0();
        __syncthreads();
        if (c + 1 < 16) load_chunk(c + 1, (c + 1) & 1);

        const uint32_t* SW0 = (const uint32_t*)(sm + (c & 1) * GST);
        const uint32_t* SW1 = SW0 + 2560;
        const uint32_t* SA  = SW0 + 5120;
#pragma unroll
        for (int ks = 0; ks < 2; ks++) {
            uint32_t awh[4][4], bb[4][2];
#pragma unroll
            for (int mt = 0; mt < 4; mt++) {
                int base = (wm * 64 + mt * 16 + qr) * 20 + qc + ks * 8;
                awh[mt][0] = SW0[base];       awh[mt][1] = SW0[base + 160];
                awh[mt][2] = SW0[base + 4];   awh[mt][3] = SW0[base + 164];
            }
#pragma unroll
            for (int nt = 0; nt < 4; nt++) {
                int bo = (wn * 32 + nt * 8 + qr) * 20 + qc + ks * 8;
                bb[nt][0] = SA[bo]; bb[nt][1] = SA[bo + 4];
            }
#pragma unroll
            for (int mt = 0; mt < 4; mt++)
#pragma unroll
                for (int nt = 0; nt < 4; nt++)
                    mma_f16(acc[mt][nt], awh[mt], bb[nt]);
            if (passes == 2) {
                uint32_t awl[4][4];
#pragma unroll
                for (int mt = 0; mt < 4; mt++) {
                    int base = (wm * 64 + mt * 16 + qr) * 20 + qc + ks * 8;
                    awl[mt][0] = SW1[base];       awl[mt][1] = SW1[base + 160];
                    awl[mt][2] = SW1[base + 4];   awl[mt][3] = SW1[base + 164];
                }
#pragma unroll
                for (int mt = 0; mt < 4; mt++)
#pragma unroll
                    for (int nt = 0; nt < 4; nt++)
                        mma_f16(acc[mt][nt], awl[mt], bb[nt]);
            }
        }
    }

    // ---- epilogue ----
    __syncthreads();
    float* Osm = (float*)sm;   // [128][132] = 67584 B (fits GSM)
    const bool tokmajor = (osel < 2);
#pragma unroll
    for (int mt = 0; mt < 4; mt++) {
        int ml = wm * 64 + mt * 16 + qr;
#pragma unroll
        for (int nt = 0; nt < 4; nt++) {
            int nl = wn * 32 + nt * 8 + qc * 2;
            if (tokmajor) {
                Osm[nl * 132 + ml]           = acc[mt][nt][0];
                Osm[(nl + 1) * 132 + ml]     = acc[mt][nt][1];
                Osm[nl * 132 + ml + 8]       = acc[mt][nt][2];
                Osm[(nl + 1) * 132 + ml + 8] = acc[mt][nt][3];
            } else {
                Osm[ml * 132 + nl]           = acc[mt][nt][0];
                Osm[ml * 132 + nl + 1]       = acc[mt][nt][1];
                Osm[(ml + 8) * 132 + nl]     = acc[mt][nt][2];
                Osm[(ml + 8) * 132 + nl + 1] = acc[mt][nt][3];
            }
        }
    }
    __syncthreads();

    if (osel <= 1) {
        __half* Oh = (osel == 0) ? g_qT : g_kT;
#pragma unroll 4
        for (int u = 0; u < 64; u++) {
            int idx = t + 256 * u;
            int tl = idx >> 7, co = idx & 127;
            int tok = n0 + tl;
            if (tok < Ntok)
                Oh[((long)b * Ntok + tok) * 512 + m0 + co] =
                    __float2half_rn(Osm[tl * 132 + co]);
        }
    } else if (osel == 2) {
#pragma unroll 4
        for (int u = 0; u < 64; u++) {
            int idx = t + 256 * u;
            int cl = idx >> 7, tl = idx & 127;
            int tok = n0 + tl;
            if (tok < Ntok)
                g_vC[((long)b * 512 + m0 + cl) * 296 + tok] =
                    __float2half_rn(Osm[cl * 132 + tl]);
        }
    } else {
#pragma unroll 4
        for (int u = 0; u < 64; u++) {
            int idx = t + 256 * u;
            int cl = idx >> 7, tl = idx & 127;
            extOut[((long)b * 512 + m0 + cl) * 4096 + n0 + tl] = Osm[cl * 132 + tl];
        }
    }
}

// ---------------------------------------------------------------------------
// Tensorized attention, single-pass fp16. Block = (bh, 128-token q-tile).
// SQ [0] 128x36w; SK [4608] 296x36w; SV [15264] 64x156w. 25248 w = 100992 B.
// ---------------------------------------------------------------------------
#define SK_  4608
#define SV_  15264
#define ATTN_SMEM (25248 * 4)

__global__ __launch_bounds__(256, 1)
void attn_kernel()
{
    extern __shared__ uint32_t smw[];
    uint4* s4 = (uint4*)smw;
    const int bh = blockIdx.y, b = bh >> 3, hh = bh & 7;
    const int n0 = blockIdx.x * 128;
    const int t = threadIdx.x, w = t >> 5, lane = t & 31;
    const int qr = lane >> 2, qc = lane & 3;

    // ---- loads (Q/K rows: 8 uint4 data, stride 9 uint4) ----
    {
        const uint4* q4 = (const uint4*)(g_qT + ((long)(b * 4096 + n0)) * 512 + hh * 64);
        for (int idx = t; idx < 1024; idx += 256) {
            int row = idx >> 3, j = idx & 7;
            s4[row * 9 + j] = q4[row * 64 + j];
        }
        const uint4* k4 = (const uint4*)(g_kT + ((long)b * 289) * 512 + hh * 64);
        for (int idx = t; idx < 2312; idx += 256) {
            int row = idx >> 3, j = idx & 7;
            s4[SK_ / 4 + row * 9 + j] = k4[row * 64 + j];
        }
        for (int idx = t; idx < 252; idx += 256)     // zero K rows 289..295
            smw[SK_ + 10404 + idx] = 0;
        const uint4* v4 = (const uint4*)(g_vC + ((long)(b * 512 + hh * 64)) * 296);
        for (int idx = t; idx < 2368; idx += 256) {
            int row = idx / 37, j = idx - row * 37;
            s4[SV_ / 4 + row * 39 + j] = v4[row * 37 + j];
        }
        for (int idx = t; idx < 512; idx += 256) {   // zero V cols 296..311
            int row = idx >> 3, ww = idx & 7;
            smw[SV_ + row * 156 + 148 + ww] = 0;
        }
    }
    __syncthreads();

    // ---- QK^T ----
    float s[37][4];
#pragma unroll
    for (int nt = 0; nt < 37; nt++)
#pragma unroll
        for (int r = 0; r < 4; r++) s[nt][r] = 0.f;

    const int qrowbase = (w * 16 + qr) * 36 + qc;
#pragma unroll
    for (int kk = 0; kk < 4; kk++) {
        int qb = qrowbase + kk * 8;
        uint32_t a[4] = { smw[qb], smw[qb + 288], smw[qb + 4], smw[qb + 292] };
        int kbase = SK_ + qr * 36 + kk * 8 + qc;
#pragma unroll
        for (int nt = 0; nt < 37; nt++) {
            int kb = kbase + nt * 288;
            uint32_t bb[2] = { smw[kb], smw[kb + 4] };
            mma_f16(s[nt], a, bb);
        }
    }

    // ---- softmax ----
    float mx0 = -1e30f, mx1 = -1e30f;
#pragma unroll
    for (int nt = 0; nt < 36; nt++) {
        mx0 = fmaxf(mx0, fmaxf(s[nt][0], s[nt][1]));
        mx1 = fmaxf(mx1, fmaxf(s[nt][2], s[nt][3]));
    }
    if (qc == 0) { mx0 = fmaxf(mx0, s[36][0]); mx1 = fmaxf(mx1, s[36][2]); }
    mx0 = fmaxf(mx0, __shfl_xor_sync(0xffffffffu, mx0, 1));
    mx0 = fmaxf(mx0, __shfl_xor_sync(0xffffffffu, mx0, 2));
    mx1 = fmaxf(mx1, __shfl_xor_sync(0xffffffffu, mx1, 1));
    mx1 = fmaxf(mx1, __shfl_xor_sync(0xffffffffu, mx1, 2));

    float sum0 = 0.f, sum1 = 0.f;
#pragma unroll
    for (int nt = 0; nt < 36; nt++) {
        float e0 = __expf(s[nt][0] - mx0), e1 = __expf(s[nt][1] - mx0);
        float e2 = __expf(s[nt][2] - mx1), e3 = __expf(s[nt][3] - mx1);
        s[nt][0] = e0; s[nt][1] = e1; s[nt][2] = e2; s[nt][3] = e3;
        sum0 += e0 + e1; sum1 += e2 + e3;
    }
    {
        float e0 = (qc == 0) ? __expf(s[36][0] - mx0) : 0.f;
        float e2 = (qc == 0) ? __expf(s[36][2] - mx1) : 0.f;
        s[36][0] = e0; s[36][1] = 0.f; s[36][2] = e2; s[36][3] = 0.f;
        sum0 += e0; sum1 += e2;
    }
    sum0 += __shfl_xor_sync(0xffffffffu, sum0, 1);
    sum0 += __shfl_xor_sync(0xffffffffu, sum0, 2);
    sum1 += __shfl_xor_sync(0xffffffffu, sum1, 1);
    sum1 += __shfl_xor_sync(0xffffffffu, sum1, 2);
    float inv0 = 1.f / sum0, inv1 = 1.f / sum1;

    // ---- P -> fp16 packed fragments ----
    uint32_t ph[38][2];
#pragma unroll
    for (int nt = 0; nt < 37; nt++) {
        ph[nt][0] = packh(s[nt][1] * inv0, s[nt][0] * inv0);
        ph[nt][1] = packh(s[nt][3] * inv1, s[nt][2] * inv1);
    }
    ph[37][0] = ph[37][1] = 0u;

    // ---- AV ----
    float o[8][4];
#pragma unroll
    for (int nt = 0; nt < 8; nt++)
#pragma unroll
        for (int r = 0; r < 4; r++) o[nt][r] = 0.f;

#pragma unroll
    for (int kc = 0; kc < 19; kc++) {
        uint32_t a[4] = { ph[2 * kc][0], ph[2 * kc][1],
                          ph[2 * kc + 1][0], ph[2 * kc + 1][1] };
        int vb0 = SV_ + qr * 156 + kc * 8 + qc;
#pragma unroll
        for (int nt = 0; nt < 8; nt++) {
            int vb = vb0 + nt * 1248;
            uint32_t bb[2] = { smw[vb], smw[vb + 4] };
            mma_f16(o[nt], a, bb);
        }
    }

    // ---- stage + store (token-major fp16) ----
    __syncthreads();
    float* Osm = (float*)smw;   // [128][68] = 34816 B < ATTN_SMEM
#pragma unroll
    for (int nt = 0; nt < 8; nt++) {
        int col = nt * 8 + qc * 2;
        int r0 = (w * 16 + qr) * 68;
        Osm[r0 + col]              = o[nt][0];
        Osm[r0 + col + 1]          = o[nt][1];
        Osm[r0 + 8 * 68 + col]     = o[nt][2];
        Osm[r0 + 8 * 68 + col + 1] = o[nt][3];
    }
    __syncthreads();
    for (int idx = t; idx < 8192; idx += 256) {
        int tok = idx >> 6, dc = idx & 63;
        g_aoT[((long)(b * 4096 + n0 + tok)) * 512 + hh * 64 + dc] =
            __float2half_rn(Osm[tok * 68 + dc]);
    }
}

// ---------------------------------------------------------------------------
// launcher
// ---------------------------------------------------------------------------
extern "C" void kernel_launch(void* const* d_in, const int* in_sizes, int n_in,
                              void* d_out, int out_size)
{
    const float* sem  = (const float*)d_in[0];
    const float* spa  = (const float*)d_in[1];
    const float* x    = (const float*)d_in[2];
    const float* wq   = (const float*)d_in[3];
    const float* wdw  = (const float*)d_in[4];
    const float* lng  = (const float*)d_in[5];
    const float* lnb  = (const float*)d_in[6];
    const float* wpw  = (const float*)d_in[7];
    const float* wout = (const float*)d_in[8];
    float* out = (float*)d_out;

    cudaFuncSetAttribute(gemm_mma, cudaFuncAttributeMaxDynamicSharedMemorySize, GSM);
    cudaFuncSetAttribute(attn_kernel, cudaFuncAttributeMaxDynamicSharedMemorySize, ATTN_SMEM);

    prep_w<<<3072, 256>>>(wq, wpw, wout);
    transpose_split<<<dim3(128, 16, 8), dim3(32, 8)>>>(sem);
    dw_kernel<<<dim3(512, 8, 2), 128>>>(spa, x, wdw);
    ln_kernel<<<dim3(289, 8, 2), 512>>>(lng, lnb);

    gemm_mma<<<dim3(32, 4, 8), 256, GSM>>>(0, 0, 0, 1, nullptr, HWQ);  // q  (1-pass)
    gemm_mma<<<dim3(3, 4, 8), 256, GSM>>>(1, 1, 1, 2, nullptr, NKV);   // k  (2-pass)
    gemm_mma<<<dim3(3, 4, 8), 256, GSM>>>(2, 1, 2, 2, nullptr, NKV);   // v  (2-pass)
    attn_kernel<<<dim3(32, 64), 256, ATTN_SMEM>>>();
    gemm_mma<<<dim3(32, 4, 8), 256, GSM>>>(3, 2, 3, 1, out, HWQ);      // out (1-pass)
}

// round 10
// speedup vs baseline: 1.2425x; 1.2425x over previous
#include <cuda_runtime.h>
#include <cuda_fp16.h>
#include <cstdint>
#include <math.h>

// ===========================================================================
// S2Attention on GB300 (sm_103 portable mma.sync path, fp16 numerics)
//   - 1x1 convs: W in fp16 hi/lo (2 MMA passes), activations single fp16,
//     3-stage cp.async pipeline (GEMMs are load-latency bound, per R9 exp)
//   - attention: single-pass fp16 HMMA
// B=8, C=512, H=W=64, HEADS=8, d=64, kv tokens 17x17=289 (pad 296)
// ===========================================================================

#define HWQ  4096
#define NKV  289

// ---------------- device scratch ----------------
__device__ __align__(256) __half g_semT [8L * 4096 * 512];  // [b][tok][512]
__device__ __align__(256) __half g_kpreT[8L * 289 * 512];
__device__ __align__(256) __half g_vpreT[8L * 289 * 512];
__device__ __align__(256) __half g_aoT  [8L * 4096 * 512];
__device__ __align__(256) __half g_qT   [8L * 4096 * 512];  // q*0.125
__device__ __align__(256) __half g_kT   [8L * 289 * 512];
__device__ __align__(256) __half g_vC   [8L * 512 * 296];   // [b][c][296] pad0
__device__ __align__(256) float  g_preK [8L * 289 * 512];   // [b][pos][c]
__device__ __align__(256) float  g_preV [8L * 289 * 512];
__device__ __align__(256) __half g_whi  [3L * 512 * 512];   // 0=wq*0.125,1=wpw,2=wout
__device__ __align__(256) __half g_wlo  [3L * 512 * 512];

// ---------------- helpers ----------------
__device__ __forceinline__ uint32_t smem_u32(const void* p) {
    uint32_t a;
    asm("{ .reg .u64 t; cvta.to.shared.u64 t, %1; cvt.u32.u64 %0, t; }"
        : "=r"(a) : "l"(p));
    return a;
}
__device__ __forceinline__ void mma_f16(float* d, const uint32_t* a, const uint32_t* b) {
    asm volatile(
        "mma.sync.aligned.m16n8k16.row.col.f32.f16.f16.f32 "
        "{%0,%1,%2,%3}, {%4,%5,%6,%7}, {%8,%9}, {%0,%1,%2,%3};"
        : "+f"(d[0]), "+f"(d[1]), "+f"(d[2]), "+f"(d[3])
        : "r"(a[0]), "r"(a[1]), "r"(a[2]), "r"(a[3]), "r"(b[0]), "r"(b[1]));
}
__device__ __forceinline__ void cpa16(uint32_t dst, const void* src, uint32_t nbytes) {
    asm volatile("cp.async.cg.shared.global [%0], [%1], 16, %2;"
                 :: "r"(dst), "l"(src), "r"(nbytes) : "memory");
}
#define CPA_COMMIT() asm volatile("cp.async.commit_group;" ::: "memory")
#define CPA_WAIT0()  asm volatile("cp.async.wait_group 0;" ::: "memory")
#define CPA_WAIT1()  asm volatile("cp.async.wait_group 1;" ::: "memory")

__device__ __forceinline__ uint32_t packh(float hi, float lo) {
    uint32_t r;
    asm("cvt.rn.f16x2.f32 %0, %1, %2;" : "=r"(r) : "f"(hi), "f"(lo));
    return r;  // lower half <- lo, upper half <- hi
}

// ---------------------------------------------------------------------------
// prep: weights -> fp16 hi/lo (wq pre-scaled by 0.125)
// ---------------------------------------------------------------------------
__global__ void prep_w(const float* __restrict__ wq, const float* __restrict__ wpw,
                       const float* __restrict__ wout)
{
    int i = blockIdx.x * 256 + threadIdx.x;
    if (i >= 3 * 262144) return;
    int widx = i >> 18, j = i & 262143;
    float v = (widx == 0) ? wq[j] * 0.125f : (widx == 1) ? wpw[j] : wout[j];
    __half h = __float2half_rn(v);
    g_whi[i] = h;
    g_wlo[i] = __float2half_rn(v - __half2float(h));
}

// ---------------------------------------------------------------------------
// transpose: sem [b][c][4096] fp32 -> g_semT fp16 [b][tok][512]
// ---------------------------------------------------------------------------
__global__ __launch_bounds__(256)
void transpose_split(const float* __restrict__ in)
{
    __shared__ float tile[32][33];
    int b = blockIdx.z, n0 = blockIdx.x * 32, c0 = blockIdx.y * 32;
    int tx = threadIdx.x, ty = threadIdx.y;
#pragma unroll
    for (int k = 0; k < 4; k++) {
        int c = c0 + ty + 8 * k;
        tile[ty + 8 * k][tx] = in[((long)b * 512 + c) * 4096 + n0 + tx];
    }
    __syncthreads();
#pragma unroll
    for (int k = 0; k < 4; k++) {
        int n = n0 + ty + 8 * k;
        g_semT[((long)b * 4096 + n) * 512 + c0 + tx] =
            __float2half_rn(tile[tx][ty + 8 * k]);
    }
}

// ---------------------------------------------------------------------------
// depthwise 4x4 s4 p2 conv, coalesced: one block per (c, b, which-input)
// ---------------------------------------------------------------------------
__global__ __launch_bounds__(128)
void dw_kernel(const float* __restrict__ in0, const float* __restrict__ in1,
               const float* __restrict__ wdw)
{
    __shared__ float plane[4096];
    const int c = blockIdx.x, b = blockIdx.y, t = threadIdx.x;
    const float* in = blockIdx.z ? in1 : in0;
    float* outp = blockIdx.z ? g_preV : g_preK;
    const float4* ip = (const float4*)(in + ((long)b * 512 + c) * 4096);
#pragma unroll
    for (int i = t; i < 1024; i += 128) ((float4*)plane)[i] = ip[i];
    float wr[16];
#pragma unroll
    for (int i = 0; i < 16; i++) wr[i] = wdw[c * 16 + i];
    __syncthreads();

    for (int pos = t; pos < 289; pos += 128) {
        int oy = pos / 17, ox = pos - oy * 17;
        float acc = 0.f;
#pragma unroll
        for (int ky = 0; ky < 4; ky++) {
            int y = oy * 4 - 2 + ky;
            if ((unsigned)y < 64u) {
#pragma unroll
                for (int kx = 0; kx < 4; kx++) {
                    int xx = ox * 4 - 2 + kx;
                    if ((unsigned)xx < 64u)
                        acc = fmaf(wr[ky * 4 + kx], plane[y * 64 + xx], acc);
                }
            }
        }
        outp[((long)b * 289 + pos) * 512 + c] = acc;
    }
}

// ---------------------------------------------------------------------------
// channel LayerNorm per token -> token-major fp16. grid (289,8,2), block 512
// ---------------------------------------------------------------------------
__global__ __launch_bounds__(512)
void ln_kernel(const float* __restrict__ lng, const float* __restrict__ lnb)
{
    const float* inp = blockIdx.z ? g_preV : g_preK;
    __half* oh = blockIdx.z ? g_vpreT : g_kpreT;
    const int pos = blockIdx.x, b = blockIdx.y, c = threadIdx.x;
    float acc = inp[((long)b * 289 + pos) * 512 + c];

    __shared__ float s1[16], s2[16];
    float v1 = acc, v2 = acc * acc;
#pragma unroll
    for (int o = 16; o > 0; o >>= 1) {
        v1 += __shfl_xor_sync(0xffffffffu, v1, o);
        v2 += __shfl_xor_sync(0xffffffffu, v2, o);
    }
    int w = threadIdx.x >> 5, lane = threadIdx.x & 31;
    if (lane == 0) { s1[w] = v1; s2[w] = v2; }
    __syncthreads();
    if (w == 0) {
        v1 = (lane < 16) ? s1[lane] : 0.f;
        v2 = (lane < 16) ? s2[lane] : 0.f;
#pragma unroll
        for (int o = 8; o > 0; o >>= 1) {
            v1 += __shfl_xor_sync(0xffffffffu, v1, o);
            v2 += __shfl_xor_sync(0xffffffffu, v2, o);
        }
        if (lane == 0) { s1[0] = v1; s2[0] = v2; }
    }
    __syncthreads();
    float mean = s1[0] * (1.f / 512.f);
    float var  = s2[0] * (1.f / 512.f) - mean * mean;
    float val  = (acc - mean) * rsqrtf(var + 1e-5f) * lng[c] + lnb[c];
    oh[((long)b * 289 + pos) * 512 + c] = __float2half_rn(val);
}

// ---------------------------------------------------------------------------
// HMMA GEMM: Out[b][tok][co] = sum_ci W[co][ci] * A[b][tok][ci]
// W fp16 hi/lo (2 MMA passes), A single fp16.
// 3-stage cp.async pipeline, wait_group 1 (two chunks in flight).
// Stages use bytes [0, 92160); fp32 epilogue staging needs 67584 B.
// ---------------------------------------------------------------------------
#define GST 30720
#define GSM 92160   // 3 * GST >= 67584 epilogue staging

__global__ __launch_bounds__(256, 1)
void gemm_mma(int asel, int widx, int osel, float* __restrict__ extOut, int Ntok)
{
    extern __shared__ char sm[];
    const uint32_t smb = smem_u32(sm);
    const int t = threadIdx.x, wid = t >> 5, lane = t & 31;
    const int qr = lane >> 2, qc = lane & 3;
    const int b = blockIdx.z, m0 = blockIdx.y * 128, n0 = blockIdx.x * 128;
    const int wm = wid >> 2, wn = wid & 3;

    const __half* A = (asel == 0) ? g_semT : (asel == 1) ? g_kpreT
                    : (asel == 2) ? g_vpreT : g_aoT;
    A += (long)b * Ntok * 512;
    const __half* Whi = g_whi + (long)widx * 262144;
    const __half* Wlo = g_wlo + (long)widx * 262144;

    float acc[4][4][4];
#pragma unroll
    for (int i = 0; i < 4; i++)
#pragma unroll
        for (int j = 0; j < 4; j++)
#pragma unroll
            for (int k = 0; k < 4; k++) acc[i][j][k] = 0.f;

    auto load_chunk = [&](int c, int stage) {
        const int k0 = c * 32;
        const uint32_t sb = smb + stage * GST;
#pragma unroll
        for (int u = 0; u < 2; u++) {
            int q = t + 256 * u;
            int row = q >> 2, cq = q & 3;
            uint32_t soff = (uint32_t)(row * 80 + cq * 16);
            long wof = ((long)(m0 + row) << 9) + k0 + cq * 8;
            cpa16(sb + soff,         Whi + wof, 16u);
            cpa16(sb + 10240 + soff, Wlo + wof, 16u);
            int tok = n0 + row;
            uint32_t asz = (tok < Ntok) ? 16u : 0u;
            long aof = ((long)(asz ? tok : 0) << 9) + k0 + cq * 8;
            cpa16(sb + 20480 + soff, A + aof, asz);
        }
        CPA_COMMIT();
    };

    load_chunk(0, 0);
    load_chunk(1, 1);

    int stage = 0;
    for (int c = 0; c < 16; c++) {
        if (c < 15) { CPA_WAIT1(); } else { CPA_WAIT0(); }
        __syncthreads();
        if (c + 2 < 16) {
            int ns = stage + 2; if (ns >= 3) ns -= 3;
            load_chunk(c + 2, ns);
        }

        const uint32_t* SW0 = (const uint32_t*)(sm + stage * GST);
        const uint32_t* SW1 = SW0 + 2560;
        const uint32_t* SA  = SW0 + 5120;
#pragma unroll
        for (int ks = 0; ks < 2; ks++) {
            uint32_t awh[4][4], awl[4][4], bb[4][2];
#pragma unroll
            for (int mt = 0; mt < 4; mt++) {
                int base = (wm * 64 + mt * 16 + qr) * 20 + qc + ks * 8;
                awh[mt][0] = SW0[base];       awh[mt][1] = SW0[base + 160];
                awh[mt][2] = SW0[base + 4];   awh[mt][3] = SW0[base + 164];
                awl[mt][0] = SW1[base];       awl[mt][1] = SW1[base + 160];
                awl[mt][2] = SW1[base + 4];   awl[mt][3] = SW1[base + 164];
            }
#pragma unroll
            for (int nt = 0; nt < 4; nt++) {
                int bo = (wn * 32 + nt * 8 + qr) * 20 + qc + ks * 8;
                bb[nt][0] = SA[bo]; bb[nt][1] = SA[bo + 4];
            }
#pragma unroll
            for (int mt = 0; mt < 4; mt++)
#pragma unroll
                for (int nt = 0; nt < 4; nt++) {
                    mma_f16(acc[mt][nt], awh[mt], bb[nt]);
                    mma_f16(acc[mt][nt], awl[mt], bb[nt]);
                }
        }
        if (++stage == 3) stage = 0;
    }

    // ---- epilogue ----
    __syncthreads();
    float* Osm = (float*)sm;   // [128][132] = 67584 B (fits GSM)
    const bool tokmajor = (osel < 2);
#pragma unroll
    for (int mt = 0; mt < 4; mt++) {
        int ml = wm * 64 + mt * 16 + qr;
#pragma unroll
        for (int nt = 0; nt < 4; nt++) {
            int nl = wn * 32 + nt * 8 + qc * 2;
            if (tokmajor) {
                Osm[nl * 132 + ml]           = acc[mt][nt][0];
                Osm[(nl + 1) * 132 + ml]     = acc[mt][nt][1];
                Osm[nl * 132 + ml + 8]       = acc[mt][nt][2];
                Osm[(nl + 1) * 132 + ml + 8] = acc[mt][nt][3];
            } else {
                Osm[ml * 132 + nl]           = acc[mt][nt][0];
                Osm[ml * 132 + nl + 1]       = acc[mt][nt][1];
                Osm[(ml + 8) * 132 + nl]     = acc[mt][nt][2];
                Osm[(ml + 8) * 132 + nl + 1] = acc[mt][nt][3];
            }
        }
    }
    __syncthreads();

    if (osel <= 1) {
        __half* Oh = (osel == 0) ? g_qT : g_kT;
#pragma unroll 4
        for (int u = 0; u < 64; u++) {
            int idx = t + 256 * u;
            int tl = idx >> 7, co = idx & 127;
            int tok = n0 + tl;
            if (tok < Ntok)
                Oh[((long)b * Ntok + tok) * 512 + m0 + co] =
                    __float2half_rn(Osm[tl * 132 + co]);
        }
    } else if (osel == 2) {
#pragma unroll 4
        for (int u = 0; u < 64; u++) {
            int idx = t + 256 * u;
            int cl = idx >> 7, tl = idx & 127;
            int tok = n0 + tl;
            if (tok < Ntok)
                g_vC[((long)b * 512 + m0 + cl) * 296 + tok] =
                    __float2half_rn(Osm[cl * 132 + tl]);
        }
    } else {
#pragma unroll 4
        for (int u = 0; u < 64; u++) {
            int idx = t + 256 * u;
            int cl = idx >> 7, tl = idx & 127;
            extOut[((long)b * 512 + m0 + cl) * 4096 + n0 + tl] = Osm[cl * 132 + tl];
        }
    }
}

// ---------------------------------------------------------------------------
// Tensorized attention, single-pass fp16. Block = (bh, 128-token q-tile).
// SQ [0] 128x36w; SK [4608] 296x36w; SV [15264] 64x156w. 25248 w = 100992 B.
// ---------------------------------------------------------------------------
#define SK_  4608
#define SV_  15264
#define ATTN_SMEM (25248 * 4)

__global__ __launch_bounds__(256, 1)
void attn_kernel()
{
    extern __shared__ uint32_t smw[];
    uint4* s4 = (uint4*)smw;
    const int bh = blockIdx.y, b = bh >> 3, hh = bh & 7;
    const int n0 = blockIdx.x * 128;
    const int t = threadIdx.x, w = t >> 5, lane = t & 31;
    const int qr = lane >> 2, qc = lane & 3;

    // ---- loads (Q/K rows: 8 uint4 data, stride 9 uint4) ----
    {
        const uint4* q4 = (const uint4*)(g_qT + ((long)(b * 4096 + n0)) * 512 + hh * 64);
        for (int idx = t; idx < 1024; idx += 256) {
            int row = idx >> 3, j = idx & 7;
            s4[row * 9 + j] = q4[row * 64 + j];
        }
        const uint4* k4 = (const uint4*)(g_kT + ((long)b * 289) * 512 + hh * 64);
        for (int idx = t; idx < 2312; idx += 256) {
            int row = idx >> 3, j = idx & 7;
            s4[SK_ / 4 + row * 9 + j] = k4[row * 64 + j];
        }
        for (int idx = t; idx < 252; idx += 256)     // zero K rows 289..295
            smw[SK_ + 10404 + idx] = 0;
        const uint4* v4 = (const uint4*)(g_vC + ((long)(b * 512 + hh * 64)) * 296);
        for (int idx = t; idx < 2368; idx += 256) {
            int row = idx / 37, j = idx - row * 37;
            s4[SV_ / 4 + row * 39 + j] = v4[row * 37 + j];
        }
        for (int idx = t; idx < 512; idx += 256) {   // zero V cols 296..311
            int row = idx >> 3, ww = idx & 7;
            smw[SV_ + row * 156 + 148 + ww] = 0;
        }
    }
    __syncthreads();

    // ---- QK^T ----
    float s[37][4];
#pragma unroll
    for (int nt = 0; nt < 37; nt++)
#pragma unroll
        for (int r = 0; r < 4; r++) s[nt][r] = 0.f;

    const int qrowbase = (w * 16 + qr) * 36 + qc;
#pragma unroll
    for (int kk = 0; kk < 4; kk++) {
        int qb = qrowbase + kk * 8;
        uint32_t a[4] = { smw[qb], smw[qb + 288], smw[qb + 4], smw[qb + 292] };
        int kbase = SK_ + qr * 36 + kk * 8 + qc;
#pragma unroll
        for (int nt = 0; nt < 37; nt++) {
            int kb = kbase + nt * 288;
            uint32_t bb[2] = { smw[kb], smw[kb + 4] };
            mma_f16(s[nt], a, bb);
        }
    }

    // ---- softmax ----
    float mx0 = -1e30f, mx1 = -1e30f;
#pragma unroll
    for (int nt = 0; nt < 36; nt++) {
        mx0 = fmaxf(mx0, fmaxf(s[nt][0], s[nt][1]));
        mx1 = fmaxf(mx1, fmaxf(s[nt][2], s[nt][3]));
    }
    if (qc == 0) { mx0 = fmaxf(mx0, s[36][0]); mx1 = fmaxf(mx1, s[36][2]); }
    mx0 = fmaxf(mx0, __shfl_xor_sync(0xffffffffu, mx0, 1));
    mx0 = fmaxf(mx0, __shfl_xor_sync(0xffffffffu, mx0, 2));
    mx1 = fmaxf(mx1, __shfl_xor_sync(0xffffffffu, mx1, 1));
    mx1 = fmaxf(mx1, __shfl_xor_sync(0xffffffffu, mx1, 2));

    float sum0 = 0.f, sum1 = 0.f;
#pragma unroll
    for (int nt = 0; nt < 36; nt++) {
        float e0 = __expf(s[nt][0] - mx0), e1 = __expf(s[nt][1] - mx0);
        float e2 = __expf(s[nt][2] - mx1), e3 = __expf(s[nt][3] - mx1);
        s[nt][0] = e0; s[nt][1] = e1; s[nt][2] = e2; s[nt][3] = e3;
        sum0 += e0 + e1; sum1 += e2 + e3;
    }
    {
        float e0 = (qc == 0) ? __expf(s[36][0] - mx0) : 0.f;
        float e2 = (qc == 0) ? __expf(s[36][2] - mx1) : 0.f;
        s[36][0] = e0; s[36][1] = 0.f; s[36][2] = e2; s[36][3] = 0.f;
        sum0 += e0; sum1 += e2;
    }
    sum0 += __shfl_xor_sync(0xffffffffu, sum0, 1);
    sum0 += __shfl_xor_sync(0xffffffffu, sum0, 2);
    sum1 += __shfl_xor_sync(0xffffffffu, sum1, 1);
    sum1 += __shfl_xor_sync(0xffffffffu, sum1, 2);
    float inv0 = 1.f / sum0, inv1 = 1.f / sum1;

    // ---- P -> fp16 packed fragments ----
    uint32_t ph[38][2];
#pragma unroll
    for (int nt = 0; nt < 37; nt++) {
        ph[nt][0] = packh(s[nt][1] * inv0, s[nt][0] * inv0);
        ph[nt][1] = packh(s[nt][3] * inv1, s[nt][2] * inv1);
    }
    ph[37][0] = ph[37][1] = 0u;

    // ---- AV ----
    float o[8][4];
#pragma unroll
    for (int nt = 0; nt < 8; nt++)
#pragma unroll
        for (int r = 0; r < 4; r++) o[nt][r] = 0.f;

#pragma unroll
    for (int kc = 0; kc < 19; kc++) {
        uint32_t a[4] = { ph[2 * kc][0], ph[2 * kc][1],
                          ph[2 * kc + 1][0], ph[2 * kc + 1][1] };
        int vb0 = SV_ + qr * 156 + kc * 8 + qc;
#pragma unroll
        for (int nt = 0; nt < 8; nt++) {
            int vb = vb0 + nt * 1248;
            uint32_t bb[2] = { smw[vb], smw[vb + 4] };
            mma_f16(o[nt], a, bb);
        }
    }

    // ---- stage + store (token-major fp16) ----
    __syncthreads();
    float* Osm = (float*)smw;   // [128][68] = 34816 B < ATTN_SMEM
#pragma unroll
    for (int nt = 0; nt < 8; nt++) {
        int col = nt * 8 + qc * 2;
        int r0 = (w * 16 + qr) * 68;
        Osm[r0 + col]              = o[nt][0];
        Osm[r0 + col + 1]          = o[nt][1];
        Osm[r0 + 8 * 68 + col]     = o[nt][2];
        Osm[r0 + 8 * 68 + col + 1] = o[nt][3];
    }
    __syncthreads();
    for (int idx = t; idx < 8192; idx += 256) {
        int tok = idx >> 6, dc = idx & 63;
        g_aoT[((long)(b * 4096 + n0 + tok)) * 512 + hh * 64 + dc] =
            __float2half_rn(Osm[tok * 68 + dc]);
    }
}

// ---------------------------------------------------------------------------
// launcher
// ---------------------------------------------------------------------------
extern "C" void kernel_launch(void* const* d_in, const int* in_sizes, int n_in,
                              void* d_out, int out_size)
{
    const float* sem  = (const float*)d_in[0];
    const float* spa  = (const float*)d_in[1];
    const float* x    = (const float*)d_in[2];
    const float* wq   = (const float*)d_in[3];
    const float* wdw  = (const float*)d_in[4];
    const float* lng  = (const float*)d_in[5];
    const float* lnb  = (const float*)d_in[6];
    const float* wpw  = (const float*)d_in[7];
    const float* wout = (const float*)d_in[8];
    float* out = (float*)d_out;

    cudaFuncSetAttribute(gemm_mma, cudaFuncAttributeMaxDynamicSharedMemorySize, GSM);
    cudaFuncSetAttribute(attn_kernel, cudaFuncAttributeMaxDynamicSharedMemorySize, ATTN_SMEM);

    prep_w<<<3072, 256>>>(wq, wpw, wout);
    transpose_split<<<dim3(128, 16, 8), dim3(32, 8)>>>(sem);
    dw_kernel<<<dim3(512, 8, 2), 128>>>(spa, x, wdw);
    ln_kernel<<<dim3(289, 8, 2), 512>>>(lng, lnb);

    gemm_mma<<<dim3(32, 4, 8), 256, GSM>>>(0, 0, 0, nullptr, HWQ);   // q
    gemm_mma<<<dim3(3, 4, 8), 256, GSM>>>(1, 1, 1, nullptr, NKV);    // k
    gemm_mma<<<dim3(3, 4, 8), 256, GSM>>>(2, 1, 2, nullptr, NKV);    // v
    attn_kernel<<<dim3(32, 64), 256, ATTN_SMEM>>>();
    gemm_mma<<<dim3(32, 4, 8), 256, GSM>>>(3, 2, 3, out, HWQ);       // out
}

// round 11
// speedup vs baseline: 1.4713x; 1.1841x over previous
#include <cuda_runtime.h>
#include <cuda_fp16.h>
#include <cstdint>
#include <math.h>

// ===========================================================================
// S2Attention on GB300 (sm_103 portable mma.sync path, fp16 numerics)
//   - q/out convs: gemm_mma<1> (single-pass fp16 W; q err enters softmax
//     absolutely, out err budgeted); k/v: gemm_mma<2> (hi/lo, latency-bound)
//   - 3-stage cp.async pipeline; compile-time pass count (no hot branches)
//   - attention: single-pass fp16 HMMA
// ===========================================================================

#define HWQ  4096
#define NKV  289

// ---------------- device scratch ----------------
__device__ __align__(256) __half g_semT [8L * 4096 * 512];  // [b][tok][512]
__device__ __align__(256) __half g_kpreT[8L * 289 * 512];
__device__ __align__(256) __half g_vpreT[8L * 289 * 512];
__device__ __align__(256) __half g_aoT  [8L * 4096 * 512];
__device__ __align__(256) __half g_qT   [8L * 4096 * 512];  // q*0.125
__device__ __align__(256) __half g_kT   [8L * 289 * 512];
__device__ __align__(256) __half g_vC   [8L * 512 * 296];   // [b][c][296] pad0
__device__ __align__(256) float  g_preK [8L * 289 * 512];   // [b][pos][c]
__device__ __align__(256) float  g_preV [8L * 289 * 512];
__device__ __align__(256) __half g_whi  [3L * 512 * 512];   // 0=wq*0.125,1=wpw,2=wout
__device__ __align__(256) __half g_wlo  [3L * 512 * 512];

// ---------------- helpers ----------------
__device__ __forceinline__ uint32_t smem_u32(const void* p) {
    uint32_t a;
    asm("{ .reg .u64 t; cvta.to.shared.u64 t, %1; cvt.u32.u64 %0, t; }"
        : "=r"(a) : "l"(p));
    return a;
}
__device__ __forceinline__ void mma_f16(float* d, const uint32_t* a, const uint32_t* b) {
    asm volatile(
        "mma.sync.aligned.m16n8k16.row.col.f32.f16.f16.f32 "
        "{%0,%1,%2,%3}, {%4,%5,%6,%7}, {%8,%9}, {%0,%1,%2,%3};"
        : "+f"(d[0]), "+f"(d[1]), "+f"(d[2]), "+f"(d[3])
        : "r"(a[0]), "r"(a[1]), "r"(a[2]), "r"(a[3]), "r"(b[0]), "r"(b[1]));
}
__device__ __forceinline__ void cpa16(uint32_t dst, const void* src, uint32_t nbytes) {
    asm volatile("cp.async.cg.shared.global [%0], [%1], 16, %2;"
                 :: "r"(dst), "l"(src), "r"(nbytes) : "memory");
}
#define CPA_COMMIT() asm volatile("cp.async.commit_group;" ::: "memory")
#define CPA_WAIT0()  asm volatile("cp.async.wait_group 0;" ::: "memory")
#define CPA_WAIT1()  asm volatile("cp.async.wait_group 1;" ::: "memory")

__device__ __forceinline__ uint32_t packh(float hi, float lo) {
    uint32_t r;
    asm("cvt.rn.f16x2.f32 %0, %1, %2;" : "=r"(r) : "f"(hi), "f"(lo));
    return r;
}

// ---------------------------------------------------------------------------
// prep: weights -> fp16 hi/lo (wq pre-scaled by 0.125)
// ---------------------------------------------------------------------------
__global__ void prep_w(const float* __restrict__ wq, const float* __restrict__ wpw,
                       const float* __restrict__ wout)
{
    int i = blockIdx.x * 256 + threadIdx.x;
    if (i >= 3 * 262144) return;
    int widx = i >> 18, j = i & 262143;
    float v = (widx == 0) ? wq[j] * 0.125f : (widx == 1) ? wpw[j] : wout[j];
    __half h = __float2half_rn(v);
    g_whi[i] = h;
    g_wlo[i] = __float2half_rn(v - __half2float(h));
}

// ---------------------------------------------------------------------------
// transpose: sem [b][c][4096] fp32 -> g_semT fp16 [b][tok][512]
// ---------------------------------------------------------------------------
__global__ __launch_bounds__(256)
void transpose_split(const float* __restrict__ in)
{
    __shared__ float tile[32][33];
    int b = blockIdx.z, n0 = blockIdx.x * 32, c0 = blockIdx.y * 32;
    int tx = threadIdx.x, ty = threadIdx.y;
#pragma unroll
    for (int k = 0; k < 4; k++) {
        int c = c0 + ty + 8 * k;
        tile[ty + 8 * k][tx] = in[((long)b * 512 + c) * 4096 + n0 + tx];
    }
    __syncthreads();
#pragma unroll
    for (int k = 0; k < 4; k++) {
        int n = n0 + ty + 8 * k;
        g_semT[((long)b * 4096 + n) * 512 + c0 + tx] =
            __float2half_rn(tile[tx][ty + 8 * k]);
    }
}

// ---------------------------------------------------------------------------
// depthwise 4x4 s4 p2 conv, coalesced: one block per (c, b, which-input)
// ---------------------------------------------------------------------------
__global__ __launch_bounds__(128)
void dw_kernel(const float* __restrict__ in0, const float* __restrict__ in1,
               const float* __restrict__ wdw)
{
    __shared__ float plane[4096];
    const int c = blockIdx.x, b = blockIdx.y, t = threadIdx.x;
    const float* in = blockIdx.z ? in1 : in0;
    float* outp = blockIdx.z ? g_preV : g_preK;
    const float4* ip = (const float4*)(in + ((long)b * 512 + c) * 4096);
#pragma unroll
    for (int i = t; i < 1024; i += 128) ((float4*)plane)[i] = ip[i];
    float wr[16];
#pragma unroll
    for (int i = 0; i < 16; i++) wr[i] = wdw[c * 16 + i];
    __syncthreads();

    for (int pos = t; pos < 289; pos += 128) {
        int oy = pos / 17, ox = pos - oy * 17;
        float acc = 0.f;
#pragma unroll
        for (int ky = 0; ky < 4; ky++) {
            int y = oy * 4 - 2 + ky;
            if ((unsigned)y < 64u) {
#pragma unroll
                for (int kx = 0; kx < 4; kx++) {
                    int xx = ox * 4 - 2 + kx;
                    if ((unsigned)xx < 64u)
                        acc = fmaf(wr[ky * 4 + kx], plane[y * 64 + xx], acc);
                }
            }
        }
        outp[((long)b * 289 + pos) * 512 + c] = acc;
    }
}

// ---------------------------------------------------------------------------
// channel LayerNorm per token -> token-major fp16. grid (289,8,2), block 512
// ---------------------------------------------------------------------------
__global__ __launch_bounds__(512)
void ln_kernel(const float* __restrict__ lng, const float* __restrict__ lnb)
{
    const float* inp = blockIdx.z ? g_preV : g_preK;
    __half* oh = blockIdx.z ? g_vpreT : g_kpreT;
    const int pos = blockIdx.x, b = blockIdx.y, c = threadIdx.x;
    float acc = inp[((long)b * 289 + pos) * 512 + c];

    __shared__ float s1[16], s2[16];
    float v1 = acc, v2 = acc * acc;
#pragma unroll
    for (int o = 16; o > 0; o >>= 1) {
        v1 += __shfl_xor_sync(0xffffffffu, v1, o);
        v2 += __shfl_xor_sync(0xffffffffu, v2, o);
    }
    int w = threadIdx.x >> 5, lane = threadIdx.x & 31;
    if (lane == 0) { s1[w] = v1; s2[w] = v2; }
    __syncthreads();
    if (w == 0) {
        v1 = (lane < 16) ? s1[lane] : 0.f;
        v2 = (lane < 16) ? s2[lane] : 0.f;
#pragma unroll
        for (int o = 8; o > 0; o >>= 1) {
            v1 += __shfl_xor_sync(0xffffffffu, v1, o);
            v2 += __shfl_xor_sync(0xffffffffu, v2, o);
        }
        if (lane == 0) { s1[0] = v1; s2[0] = v2; }
    }
    __syncthreads();
    float mean = s1[0] * (1.f / 512.f);
    float var  = s2[0] * (1.f / 512.f) - mean * mean;
    float val  = (acc - mean) * rsqrtf(var + 1e-5f) * lng[c] + lnb[c];
    oh[((long)b * 289 + pos) * 512 + c] = __float2half_rn(val);
}

// ---------------------------------------------------------------------------
// HMMA GEMM: Out[b][tok][co] = sum_ci W[co][ci] * A[b][tok][ci]
// PASSES compile-time: 1 = W hi only; 2 = W hi + lo.
// z encodes (kv, b): b = z&7, sel offset = z>>3 (0 for 8-deep grids).
// 3-stage cp.async pipeline, wait_group 1.
// ---------------------------------------------------------------------------
#define GST 30720
#define GSM 92160   // 3 * GST; epilogue staging 67584 B fits

template<int PASSES>
__global__ __launch_bounds__(256, 1)
void gemm_mma(int asel, int widx, int osel, float* __restrict__ extOut, int Ntok)
{
    extern __shared__ char sm[];
    const uint32_t smb = smem_u32(sm);
    const int t = threadIdx.x, wid = t >> 5, lane = t & 31;
    const int qr = lane >> 2, qc = lane & 3;
    const int b = blockIdx.z & 7, zsel = blockIdx.z >> 3;
    const int m0 = blockIdx.y * 128, n0 = blockIdx.x * 128;
    const int wm = wid >> 2, wn = wid & 3;
    const int aselE = asel + zsel, oselE = osel + zsel;

    const __half* A = (aselE == 0) ? g_semT : (aselE == 1) ? g_kpreT
                    : (aselE == 2) ? g_vpreT : g_aoT;
    A += (long)b * Ntok * 512;
    const __half* Whi = g_whi + (long)widx * 262144;
    const __half* Wlo = g_wlo + (long)widx * 262144;

    float acc[4][4][4];
#pragma unroll
    for (int i = 0; i < 4; i++)
#pragma unroll
        for (int j = 0; j < 4; j++)
#pragma unroll
            for (int k = 0; k < 4; k++) acc[i][j][k] = 0.f;

    auto load_chunk = [&](int c, int stage) {
        const int k0 = c * 32;
        const uint32_t sb = smb + stage * GST;
#pragma unroll
        for (int u = 0; u < 2; u++) {
            int q = t + 256 * u;
            int row = q >> 2, cq = q & 3;
            uint32_t soff = (uint32_t)(row * 80 + cq * 16);
            long wof = ((long)(m0 + row) << 9) + k0 + cq * 8;
            cpa16(sb + soff, Whi + wof, 16u);
            if (PASSES == 2) cpa16(sb + 10240 + soff, Wlo + wof, 16u);
            int tok = n0 + row;
            uint32_t asz = (tok < Ntok) ? 16u : 0u;
            long aof = ((long)(asz ? tok : 0) << 9) + k0 + cq * 8;
            cpa16(sb + 20480 + soff, A + aof, asz);
        }
        CPA_COMMIT();
    };

    load_chunk(0, 0);
    load_chunk(1, 1);

    int stage = 0;
    for (int c = 0; c < 16; c++) {
        if (c < 15) { CPA_WAIT1(); } else { CPA_WAIT0(); }
        __syncthreads();
        if (c + 2 < 16) {
            int ns = stage + 2; if (ns >= 3) ns -= 3;
            load_chunk(c + 2, ns);
        }

        const uint32_t* SW0 = (const uint32_t*)(sm + stage * GST);
        const uint32_t* SW1 = SW0 + 2560;
        const uint32_t* SA  = SW0 + 5120;
#pragma unroll
        for (int ks = 0; ks < 2; ks++) {
            uint32_t awh[4][4], bb[4][2];
#pragma unroll
            for (int mt = 0; mt < 4; mt++) {
                int base = (wm * 64 + mt * 16 + qr) * 20 + qc + ks * 8;
                awh[mt][0] = SW0[base];       awh[mt][1] = SW0[base + 160];
                awh[mt][2] = SW0[base + 4];   awh[mt][3] = SW0[base + 164];
            }
#pragma unroll
            for (int nt = 0; nt < 4; nt++) {
                int bo = (wn * 32 + nt * 8 + qr) * 20 + qc + ks * 8;
                bb[nt][0] = SA[bo]; bb[nt][1] = SA[bo + 4];
            }
#pragma unroll
            for (int mt = 0; mt < 4; mt++)
#pragma unroll
                for (int nt = 0; nt < 4; nt++)
                    mma_f16(acc[mt][nt], awh[mt], bb[nt]);
            if (PASSES == 2) {
                uint32_t awl[4][4];
#pragma unroll
                for (int mt = 0; mt < 4; mt++) {
                    int base = (wm * 64 + mt * 16 + qr) * 20 + qc + ks * 8;
                    awl[mt][0] = SW1[base];       awl[mt][1] = SW1[base + 160];
                    awl[mt][2] = SW1[base + 4];   awl[mt][3] = SW1[base + 164];
                }
#pragma unroll
                for (int mt = 0; mt < 4; mt++)
#pragma unroll
                    for (int nt = 0; nt < 4; nt++)
                        mma_f16(acc[mt][nt], awl[mt], bb[nt]);
            }
        }
        if (++stage == 3) stage = 0;
    }

    // ---- epilogue ----
    __syncthreads();
    float* Osm = (float*)sm;   // [128][132]
    const bool tokmajor = (oselE < 2);
#pragma unroll
    for (int mt = 0; mt < 4; mt++) {
        int ml = wm * 64 + mt * 16 + qr;
#pragma unroll
        for (int nt = 0; nt < 4; nt++) {
            int nl = wn * 32 + nt * 8 + qc * 2;
            if (tokmajor) {
                Osm[nl * 132 + ml]           = acc[mt][nt][0];
                Osm[(nl + 1) * 132 + ml]     = acc[mt][nt][1];
                Osm[nl * 132 + ml + 8]       = acc[mt][nt][2];
                Osm[(nl + 1) * 132 + ml + 8] = acc[mt][nt][3];
            } else {
                Osm[ml * 132 + nl]           = acc[mt][nt][0];
                Osm[ml * 132 + nl + 1]       = acc[mt][nt][1];
                Osm[(ml + 8) * 132 + nl]     = acc[mt][nt][2];
                Osm[(ml + 8) * 132 + nl + 1] = acc[mt][nt][3];
            }
        }
    }
    __syncthreads();

    if (oselE <= 1) {
        __half* Oh = (oselE == 0) ? g_qT : g_kT;
#pragma unroll 4
        for (int u = 0; u < 64; u++) {
            int idx = t + 256 * u;
            int tl = idx >> 7, co = idx & 127;
            int tok = n0 + tl;
            if (tok < Ntok)
                Oh[((long)b * Ntok + tok) * 512 + m0 + co] =
                    __float2half_rn(Osm[tl * 132 + co]);
        }
    } else if (oselE == 2) {
#pragma unroll 4
        for (int u = 0; u < 64; u++) {
            int idx = t + 256 * u;
            int cl = idx >> 7, tl = idx & 127;
            int tok = n0 + tl;
            if (tok < Ntok)
                g_vC[((long)b * 512 + m0 + cl) * 296 + tok] =
                    __float2half_rn(Osm[cl * 132 + tl]);
        }
    } else {
#pragma unroll 4
        for (int u = 0; u < 64; u++) {
            int idx = t + 256 * u;
            int cl = idx >> 7, tl = idx & 127;
            extOut[((long)b * 512 + m0 + cl) * 4096 + n0 + tl] = Osm[cl * 132 + tl];
        }
    }
}

// ---------------------------------------------------------------------------
// Tensorized attention, single-pass fp16. Block = (bh, 128-token q-tile).
// SQ [0] 128x36w; SK [4608] 296x36w; SV [15264] 64x156w. 25248 w = 100992 B.
// ---------------------------------------------------------------------------
#define SK_  4608
#define SV_  15264
#define ATTN_SMEM (25248 * 4)

__global__ __launch_bounds__(256, 1)
void attn_kernel()
{
    extern __shared__ uint32_t smw[];
    uint4* s4 = (uint4*)smw;
    const int bh = blockIdx.y, b = bh >> 3, hh = bh & 7;
    const int n0 = blockIdx.x * 128;
    const int t = threadIdx.x, w = t >> 5, lane = t & 31;
    const int qr = lane >> 2, qc = lane & 3;

    {
        const uint4* q4 = (const uint4*)(g_qT + ((long)(b * 4096 + n0)) * 512 + hh * 64);
        for (int idx = t; idx < 1024; idx += 256) {
            int row = idx >> 3, j = idx & 7;
            s4[row * 9 + j] = q4[row * 64 + j];
        }
        const uint4* k4 = (const uint4*)(g_kT + ((long)b * 289) * 512 + hh * 64);
        for (int idx = t; idx < 2312; idx += 256) {
            int row = idx >> 3, j = idx & 7;
            s4[SK_ / 4 + row * 9 + j] = k4[row * 64 + j];
        }
        for (int idx = t; idx < 252; idx += 256)
            smw[SK_ + 10404 + idx] = 0;
        const uint4* v4 = (const uint4*)(g_vC + ((long)(b * 512 + hh * 64)) * 296);
        for (int idx = t; idx < 2368; idx += 256) {
            int row = idx / 37, j = idx - row * 37;
            s4[SV_ / 4 + row * 39 + j] = v4[row * 37 + j];
        }
        for (int idx = t; idx < 512; idx += 256) {
            int row = idx >> 3, ww = idx & 7;
            smw[SV_ + row * 156 + 148 + ww] = 0;
        }
    }
    __syncthreads();

    float s[37][4];
#pragma unroll
    for (int nt = 0; nt < 37; nt++)
#pragma unroll
        for (int r = 0; r < 4; r++) s[nt][r] = 0.f;

    const int qrowbase = (w * 16 + qr) * 36 + qc;
#pragma unroll
    for (int kk = 0; kk < 4; kk++) {
        int qb = qrowbase + kk * 8;
        uint32_t a[4] = { smw[qb], smw[qb + 288], smw[qb + 4], smw[qb + 292] };
        int kbase = SK_ + qr * 36 + kk * 8 + qc;
#pragma unroll
        for (int nt = 0; nt < 37; nt++) {
            int kb = kbase + nt * 288;
            uint32_t bb[2] = { smw[kb], smw[kb + 4] };
            mma_f16(s[nt], a, bb);
        }
    }

    float mx0 = -1e30f, mx1 = -1e30f;
#pragma unroll
    for (int nt = 0; nt < 36; nt++) {
        mx0 = fmaxf(mx0, fmaxf(s[nt][0], s[nt][1]));
        mx1 = fmaxf(mx1, fmaxf(s[nt][2], s[nt][3]));
    }
    if (qc == 0) { mx0 = fmaxf(mx0, s[36][0]); mx1 = fmaxf(mx1, s[36][2]); }
    mx0 = fmaxf(mx0, __shfl_xor_sync(0xffffffffu, mx0, 1));
    mx0 = fmaxf(mx0, __shfl_xor_sync(0xffffffffu, mx0, 2));
    mx1 = fmaxf(mx1, __shfl_xor_sync(0xffffffffu, mx1, 1));
    mx1 = fmaxf(mx1, __shfl_xor_sync(0xffffffffu, mx1, 2));

    float sum0 = 0.f, sum1 = 0.f;
#pragma unroll
    for (int nt = 0; nt < 36; nt++) {
        float e0 = __expf(s[nt][0] - mx0), e1 = __expf(s[nt][1] - mx0);
        float e2 = __expf(s[nt][2] - mx1), e3 = __expf(s[nt][3] - mx1);
        s[nt][0] = e0; s[nt][1] = e1; s[nt][2] = e2; s[nt][3] = e3;
        sum0 += e0 + e1; sum1 += e2 + e3;
    }
    {
        float e0 = (qc == 0) ? __expf(s[36][0] - mx0) : 0.f;
        float e2 = (qc == 0) ? __expf(s[36][2] - mx1) : 0.f;
        s[36][0] = e0; s[36][1] = 0.f; s[36][2] = e2; s[36][3] = 0.f;
        sum0 += e0; sum1 += e2;
    }
    sum0 += __shfl_xor_sync(0xffffffffu, sum0, 1);
    sum0 += __shfl_xor_sync(0xffffffffu, sum0, 2);
    sum1 += __shfl_xor_sync(0xffffffffu, sum1, 1);
    sum1 += __shfl_xor_sync(0xffffffffu, sum1, 2);
    float inv0 = 1.f / sum0, inv1 = 1.f / sum1;

    uint32_t ph[38][2];
#pragma unroll
    for (int nt = 0; nt < 37; nt++) {
        ph[nt][0] = packh(s[nt][1] * inv0, s[nt][0] * inv0);
        ph[nt][1] = packh(s[nt][3] * inv1, s[nt][2] * inv1);
    }
    ph[37][0] = ph[37][1] = 0u;

    float o[8][4];
#pragma unroll
    for (int nt = 0; nt < 8; nt++)
#pragma unroll
        for (int r = 0; r < 4; r++) o[nt][r] = 0.f;

#pragma unroll
    for (int kc = 0; kc < 19; kc++) {
        uint32_t a[4] = { ph[2 * kc][0], ph[2 * kc][1],
                          ph[2 * kc + 1][0], ph[2 * kc + 1][1] };
        int vb0 = SV_ + qr * 156 + kc * 8 + qc;
#pragma unroll
        for (int nt = 0; nt < 8; nt++) {
            int vb = vb0 + nt * 1248;
            uint32_t bb[2] = { smw[vb], smw[vb + 4] };
            mma_f16(o[nt], a, bb);
        }
    }

    __syncthreads();
    float* Osm = (float*)smw;   // [128][68]
#pragma unroll
    for (int nt = 0; nt < 8; nt++) {
        int col = nt * 8 + qc * 2;
        int r0 = (w * 16 + qr) * 68;
        Osm[r0 + col]              = o[nt][0];
        Osm[r0 + col + 1]          = o[nt][1];
        Osm[r0 + 8 * 68 + col]     = o[nt][2];
        Osm[r0 + 8 * 68 + col + 1] = o[nt][3];
    }
    __syncthreads();
    for (int idx = t; idx < 8192; idx += 256) {
        int tok = idx >> 6, dc = idx & 63;
        g_aoT[((long)(b * 4096 + n0 + tok)) * 512 + hh * 64 + dc] =
            __float2half_rn(Osm[tok * 68 + dc]);
    }
}

// ---------------------------------------------------------------------------
// launcher
// ---------------------------------------------------------------------------
extern "C" void kernel_launch(void* const* d_in, const int* in_sizes, int n_in,
                              void* d_out, int out_size)
{
    const float* sem  = (const float*)d_in[0];
    const float* spa  = (const float*)d_in[1];
    const float* x    = (const float*)d_in[2];
    const float* wq   = (const float*)d_in[3];
    const float* wdw  = (const float*)d_in[4];
    const float* lng  = (const float*)d_in[5];
    const float* lnb  = (const float*)d_in[6];
    const float* wpw  = (const float*)d_in[7];
    const float* wout = (const float*)d_in[8];
    float* out = (float*)d_out;

    cudaFuncSetAttribute(gemm_mma<1>, cudaFuncAttributeMaxDynamicSharedMemorySize, GSM);
    cudaFuncSetAttribute(gemm_mma<2>, cudaFuncAttributeMaxDynamicSharedMemorySize, GSM);
    cudaFuncSetAttribute(attn_kernel, cudaFuncAttributeMaxDynamicSharedMemorySize, ATTN_SMEM);

    prep_w<<<3072, 256>>>(wq, wpw, wout);
    transpose_split<<<dim3(128, 16, 8), dim3(32, 8)>>>(sem);
    dw_kernel<<<dim3(512, 8, 2), 128>>>(spa, x, wdw);
    ln_kernel<<<dim3(289, 8, 2), 512>>>(lng, lnb);

    // q (1-pass)
    gemm_mma<1><<<dim3(32, 4, 8), 256, GSM>>>(0, 0, 0, nullptr, HWQ);
    // k + v merged (2-pass): z = b + 8*kv -> asel/osel 1 or 2
    gemm_mma<2><<<dim3(3, 4, 16), 256, GSM>>>(1, 1, 1, nullptr, NKV);
    attn_kernel<<<dim3(32, 64), 256, ATTN_SMEM>>>();
    // out (1-pass)
    gemm_mma<1><<<dim3(32, 4, 8), 256, GSM>>>(3, 2, 3, out, HWQ);
}

// round 12
// speedup vs baseline: 1.5177x; 1.0315x over previous
#include <cuda_runtime.h>
#include <cuda_fp16.h>
#include <cstdint>
#include <math.h>

// ===========================================================================
// S2Attention on GB300 (sm_103 portable mma.sync path, fp16 numerics)
//   - q/out convs: gemm_mma<1> (single-pass fp16 W); k/v: gemm_mma<2> (hi/lo)
//   - K-chunk 64 (2x 32-k subtiles), 3-stage cp.async pipeline
//   - attention: single-pass fp16 HMMA, P packed in-loop (no spills)
// ===========================================================================

#define HWQ  4096
#define NKV  289

// ---------------- device scratch ----------------
__device__ __align__(256) __half g_semT [8L * 4096 * 512];  // [b][tok][512]
__device__ __align__(256) __half g_kpreT[8L * 289 * 512];
__device__ __align__(256) __half g_vpreT[8L * 289 * 512];
__device__ __align__(256) __half g_aoT  [8L * 4096 * 512];
__device__ __align__(256) __half g_qT   [8L * 4096 * 512];  // q*0.125
__device__ __align__(256) __half g_kT   [8L * 289 * 512];
__device__ __align__(256) __half g_vC   [8L * 512 * 296];   // [b][c][296] pad0
__device__ __align__(256) float  g_preK [8L * 289 * 512];   // [b][pos][c]
__device__ __align__(256) float  g_preV [8L * 289 * 512];
__device__ __align__(256) __half g_whi  [3L * 512 * 512];   // 0=wq*0.125,1=wpw,2=wout
__device__ __align__(256) __half g_wlo  [3L * 512 * 512];

// ---------------- helpers ----------------
__device__ __forceinline__ uint32_t smem_u32(const void* p) {
    uint32_t a;
    asm("{ .reg .u64 t; cvta.to.shared.u64 t, %1; cvt.u32.u64 %0, t; }"
        : "=r"(a) : "l"(p));
    return a;
}
__device__ __forceinline__ void mma_f16(float* d, const uint32_t* a, const uint32_t* b) {
    asm volatile(
        "mma.sync.aligned.m16n8k16.row.col.f32.f16.f16.f32 "
        "{%0,%1,%2,%3}, {%4,%5,%6,%7}, {%8,%9}, {%0,%1,%2,%3};"
        : "+f"(d[0]), "+f"(d[1]), "+f"(d[2]), "+f"(d[3])
        : "r"(a[0]), "r"(a[1]), "r"(a[2]), "r"(a[3]), "r"(b[0]), "r"(b[1]));
}
__device__ __forceinline__ void cpa16(uint32_t dst, const void* src, uint32_t nbytes) {
    asm volatile("cp.async.cg.shared.global [%0], [%1], 16, %2;"
                 :: "r"(dst), "l"(src), "r"(nbytes) : "memory");
}
#define CPA_COMMIT() asm volatile("cp.async.commit_group;" ::: "memory")
#define CPA_WAIT0()  asm volatile("cp.async.wait_group 0;" ::: "memory")
#define CPA_WAIT1()  asm volatile("cp.async.wait_group 1;" ::: "memory")

__device__ __forceinline__ uint32_t packh(float hi, float lo) {
    uint32_t r;
    asm("cvt.rn.f16x2.f32 %0, %1, %2;" : "=r"(r) : "f"(hi), "f"(lo));
    return r;
}

// ---------------------------------------------------------------------------
// prep: weights -> fp16 hi/lo (wq pre-scaled by 0.125)
// ---------------------------------------------------------------------------
__global__ void prep_w(const float* __restrict__ wq, const float* __restrict__ wpw,
                       const float* __restrict__ wout)
{
    int i = blockIdx.x * 256 + threadIdx.x;
    if (i >= 3 * 262144) return;
    int widx = i >> 18, j = i & 262143;
    float v = (widx == 0) ? wq[j] * 0.125f : (widx == 1) ? wpw[j] : wout[j];
    __half h = __float2half_rn(v);
    g_whi[i] = h;
    g_wlo[i] = __float2half_rn(v - __half2float(h));
}

// ---------------------------------------------------------------------------
// transpose: sem [b][c][4096] fp32 -> g_semT fp16 [b][tok][512]
// ---------------------------------------------------------------------------
__global__ __launch_bounds__(256)
void transpose_split(const float* __restrict__ in)
{
    __shared__ float tile[32][33];
    int b = blockIdx.z, n0 = blockIdx.x * 32, c0 = blockIdx.y * 32;
    int tx = threadIdx.x, ty = threadIdx.y;
#pragma unroll
    for (int k = 0; k < 4; k++) {
        int c = c0 + ty + 8 * k;
        tile[ty + 8 * k][tx] = in[((long)b * 512 + c) * 4096 + n0 + tx];
    }
    __syncthreads();
#pragma unroll
    for (int k = 0; k < 4; k++) {
        int n = n0 + ty + 8 * k;
        g_semT[((long)b * 4096 + n) * 512 + c0 + tx] =
            __float2half_rn(tile[tx][ty + 8 * k]);
    }
}

// ---------------------------------------------------------------------------
// depthwise 4x4 s4 p2 conv, coalesced: one block per (c, b, which-input)
// ---------------------------------------------------------------------------
__global__ __launch_bounds__(128)
void dw_kernel(const float* __restrict__ in0, const float* __restrict__ in1,
               const float* __restrict__ wdw)
{
    __shared__ float plane[4096];
    const int c = blockIdx.x, b = blockIdx.y, t = threadIdx.x;
    const float* in = blockIdx.z ? in1 : in0;
    float* outp = blockIdx.z ? g_preV : g_preK;
    const float4* ip = (const float4*)(in + ((long)b * 512 + c) * 4096);
#pragma unroll
    for (int i = t; i < 1024; i += 128) ((float4*)plane)[i] = ip[i];
    float wr[16];
#pragma unroll
    for (int i = 0; i < 16; i++) wr[i] = wdw[c * 16 + i];
    __syncthreads();

    for (int pos = t; pos < 289; pos += 128) {
        int oy = pos / 17, ox = pos - oy * 17;
        float acc = 0.f;
#pragma unroll
        for (int ky = 0; ky < 4; ky++) {
            int y = oy * 4 - 2 + ky;
            if ((unsigned)y < 64u) {
#pragma unroll
                for (int kx = 0; kx < 4; kx++) {
                    int xx = ox * 4 - 2 + kx;
                    if ((unsigned)xx < 64u)
                        acc = fmaf(wr[ky * 4 + kx], plane[y * 64 + xx], acc);
                }
            }
        }
        outp[((long)b * 289 + pos) * 512 + c] = acc;
    }
}

// ---------------------------------------------------------------------------
// channel LayerNorm per token -> token-major fp16. grid (289,8,2), block 512
// ---------------------------------------------------------------------------
__global__ __launch_bounds__(512)
void ln_kernel(const float* __restrict__ lng, const float* __restrict__ lnb)
{
    const float* inp = blockIdx.z ? g_preV : g_preK;
    __half* oh = blockIdx.z ? g_vpreT : g_kpreT;
    const int pos = blockIdx.x, b = blockIdx.y, c = threadIdx.x;
    float acc = inp[((long)b * 289 + pos) * 512 + c];

    __shared__ float s1[16], s2[16];
    float v1 = acc, v2 = acc * acc;
#pragma unroll
    for (int o = 16; o > 0; o >>= 1) {
        v1 += __shfl_xor_sync(0xffffffffu, v1, o);
        v2 += __shfl_xor_sync(0xffffffffu, v2, o);
    }
    int w = threadIdx.x >> 5, lane = threadIdx.x & 31;
    if (lane == 0) { s1[w] = v1; s2[w] = v2; }
    __syncthreads();
    if (w == 0) {
        v1 = (lane < 16) ? s1[lane] : 0.f;
        v2 = (lane < 16) ? s2[lane] : 0.f;
#pragma unroll
        for (int o = 8; o > 0; o >>= 1) {
            v1 += __shfl_xor_sync(0xffffffffu, v1, o);
            v2 += __shfl_xor_sync(0xffffffffu, v2, o);
        }
        if (lane == 0) { s1[0] = v1; s2[0] = v2; }
    }
    __syncthreads();
    float mean = s1[0] * (1.f / 512.f);
    float var  = s2[0] * (1.f / 512.f) - mean * mean;
    float val  = (acc - mean) * rsqrtf(var + 1e-5f) * lng[c] + lnb[c];
    oh[((long)b * 289 + pos) * 512 + c] = __float2half_rn(val);
}

// ---------------------------------------------------------------------------
// HMMA GEMM: Out[b][tok][co] = sum_ci W[co][ci] * A[b][tok][ci]
// K-chunk 64 = 2x 32-k subtiles; 3-stage pipeline; PASSES compile-time.
// Subtile layout (bytes): [Whi 10240][(Wlo 10240 if P2)][A 10240]
// ---------------------------------------------------------------------------
template<int PASSES>
__global__ __launch_bounds__(256, 1)
void gemm_mma(int asel, int widx, int osel, float* __restrict__ extOut, int Ntok)
{
    constexpr int SUB  = (PASSES + 1) * 10240;   // bytes per 32-k subtile set
    constexpr int GSTP = 2 * SUB;                // per 64-k chunk stage
    extern __shared__ char sm[];
    const uint32_t smb = smem_u32(sm);
    const int t = threadIdx.x, wid = t >> 5, lane = t & 31;
    const int qr = lane >> 2, qc = lane & 3;
    const int b = blockIdx.z & 7, zsel = blockIdx.z >> 3;
    const int m0 = blockIdx.y * 128, n0 = blockIdx.x * 128;
    const int wm = wid >> 2, wn = wid & 3;
    const int aselE = asel + zsel, oselE = osel + zsel;

    const __half* A = (aselE == 0) ? g_semT : (aselE == 1) ? g_kpreT
                    : (aselE == 2) ? g_vpreT : g_aoT;
    A += (long)b * Ntok * 512;
    const __half* Whi = g_whi + (long)widx * 262144;
    const __half* Wlo = g_wlo + (long)widx * 262144;

    float acc[4][4][4];
#pragma unroll
    for (int i = 0; i < 4; i++)
#pragma unroll
        for (int j = 0; j < 4; j++)
#pragma unroll
            for (int k = 0; k < 4; k++) acc[i][j][k] = 0.f;

    auto load_sub = [&](int k0s, uint32_t sb) {
#pragma unroll
        for (int u = 0; u < 2; u++) {
            int q = t + 256 * u;
            int row = q >> 2, cq = q & 3;
            uint32_t soff = (uint32_t)(row * 80 + cq * 16);
            long wof = ((long)(m0 + row) << 9) + k0s + cq * 8;
            cpa16(sb + soff, Whi + wof, 16u);
            if (PASSES == 2) cpa16(sb + 10240 + soff, Wlo + wof, 16u);
            int tok = n0 + row;
            uint32_t asz = (tok < Ntok) ? 16u : 0u;
            long aof = ((long)(asz ? tok : 0) << 9) + k0s + cq * 8;
            cpa16(sb + (PASSES == 2 ? 20480 : 10240) + soff, A + aof, asz);
        }
    };
    auto load_chunk = [&](int c, int stage) {
        uint32_t sb = smb + stage * GSTP;
        load_sub(c * 64, sb);
        load_sub(c * 64 + 32, sb + SUB);
        CPA_COMMIT();
    };

    load_chunk(0, 0);
    load_chunk(1, 1);

    int stage = 0;
    for (int c = 0; c < 8; c++) {
        if (c < 7) { CPA_WAIT1(); } else { CPA_WAIT0(); }
        __syncthreads();
        if (c + 2 < 8) {
            int ns = stage + 2; if (ns >= 3) ns -= 3;
            load_chunk(c + 2, ns);
        }

        const char* stb = sm + stage * GSTP;
#pragma unroll
        for (int sub = 0; sub < 2; sub++) {
            const uint32_t* SW0 = (const uint32_t*)(stb + sub * SUB);
            const uint32_t* SW1 = SW0 + 2560;
            const uint32_t* SA  = SW0 + (PASSES == 2 ? 5120 : 2560);
#pragma unroll
            for (int ks = 0; ks < 2; ks++) {
                uint32_t awh[4][4], bb[4][2];
#pragma unroll
                for (int mt = 0; mt < 4; mt++) {
                    int base = (wm * 64 + mt * 16 + qr) * 20 + qc + ks * 8;
                    awh[mt][0] = SW0[base];       awh[mt][1] = SW0[base + 160];
                    awh[mt][2] = SW0[base + 4];   awh[mt][3] = SW0[base + 164];
                }
#pragma unroll
                for (int nt = 0; nt < 4; nt++) {
                    int bo = (wn * 32 + nt * 8 + qr) * 20 + qc + ks * 8;
                    bb[nt][0] = SA[bo]; bb[nt][1] = SA[bo + 4];
                }
#pragma unroll
                for (int mt = 0; mt < 4; mt++)
#pragma unroll
                    for (int nt = 0; nt < 4; nt++)
                        mma_f16(acc[mt][nt], awh[mt], bb[nt]);
                if (PASSES == 2) {
                    uint32_t awl[4][4];
#pragma unroll
                    for (int mt = 0; mt < 4; mt++) {
                        int base = (wm * 64 + mt * 16 + qr) * 20 + qc + ks * 8;
                        awl[mt][0] = SW1[base];       awl[mt][1] = SW1[base + 160];
                        awl[mt][2] = SW1[base + 4];   awl[mt][3] = SW1[base + 164];
                    }
#pragma unroll
                    for (int mt = 0; mt < 4; mt++)
#pragma unroll
                        for (int nt = 0; nt < 4; nt++)
                            mma_f16(acc[mt][nt], awl[mt], bb[nt]);
                }
            }
        }
        if (++stage == 3) stage = 0;
    }

    // ---- epilogue ----
    __syncthreads();
    float* Osm = (float*)sm;   // [128][132] = 67584 B (fits all GSM variants)
    const bool tokmajor = (oselE < 2);
#pragma unroll
    for (int mt = 0; mt < 4; mt++) {
        int ml = wm * 64 + mt * 16 + qr;
#pragma unroll
        for (int nt = 0; nt < 4; nt++) {
            int nl = wn * 32 + nt * 8 + qc * 2;
            if (tokmajor) {
                Osm[nl * 132 + ml]           = acc[mt][nt][0];
                Osm[(nl + 1) * 132 + ml]     = acc[mt][nt][1];
                Osm[nl * 132 + ml + 8]       = acc[mt][nt][2];
                Osm[(nl + 1) * 132 + ml + 8] = acc[mt][nt][3];
            } else {
                Osm[ml * 132 + nl]           = acc[mt][nt][0];
                Osm[ml * 132 + nl + 1]       = acc[mt][nt][1];
                Osm[(ml + 8) * 132 + nl]     = acc[mt][nt][2];
                Osm[(ml + 8) * 132 + nl + 1] = acc[mt][nt][3];
            }
        }
    }
    __syncthreads();

    if (oselE <= 1) {
        __half* Oh = (oselE == 0) ? g_qT : g_kT;
#pragma unroll 4
        for (int u = 0; u < 64; u++) {
            int idx = t + 256 * u;
            int tl = idx >> 7, co = idx & 127;
            int tok = n0 + tl;
            if (tok < Ntok)
                Oh[((long)b * Ntok + tok) * 512 + m0 + co] =
                    __float2half_rn(Osm[tl * 132 + co]);
        }
    } else if (oselE == 2) {
#pragma unroll 4
        for (int u = 0; u < 64; u++) {
            int idx = t + 256 * u;
            int cl = idx >> 7, tl = idx & 127;
            int tok = n0 + tl;
            if (tok < Ntok)
                g_vC[((long)b * 512 + m0 + cl) * 296 + tok] =
                    __float2half_rn(Osm[cl * 132 + tl]);
        }
    } else {
#pragma unroll 4
        for (int u = 0; u < 64; u++) {
            int idx = t + 256 * u;
            int cl = idx >> 7, tl = idx & 127;
            extOut[((long)b * 512 + m0 + cl) * 4096 + n0 + tl] = Osm[cl * 132 + tl];
        }
    }
}

// ---------------------------------------------------------------------------
// Tensorized attention, single-pass fp16. Block = (bh, 128-token q-tile).
// SQ [0] 128x36w; SK [4608] 296x36w; SV [15264] 64x156w. 25248 w = 100992 B.
// P fragments packed inside the AV loop (no ph array -> no spills).
// ---------------------------------------------------------------------------
#define SK_  4608
#define SV_  15264
#define ATTN_SMEM (25248 * 4)

__global__ __launch_bounds__(256, 1)
void attn_kernel()
{
    extern __shared__ uint32_t smw[];
    uint4* s4 = (uint4*)smw;
    const int bh = blockIdx.y, b = bh >> 3, hh = bh & 7;
    const int n0 = blockIdx.x * 128;
    const int t = threadIdx.x, w = t >> 5, lane = t & 31;
    const int qr = lane >> 2, qc = lane & 3;

    {
        const uint4* q4 = (const uint4*)(g_qT + ((long)(b * 4096 + n0)) * 512 + hh * 64);
        for (int idx = t; idx < 1024; idx += 256) {
            int row = idx >> 3, j = idx & 7;
            s4[row * 9 + j] = q4[row * 64 + j];
        }
        const uint4* k4 = (const uint4*)(g_kT + ((long)b * 289) * 512 + hh * 64);
        for (int idx = t; idx < 2312; idx += 256) {
            int row = idx >> 3, j = idx & 7;
            s4[SK_ / 4 + row * 9 + j] = k4[row * 64 + j];
        }
        for (int idx = t; idx < 252; idx += 256)
            smw[SK_ + 10404 + idx] = 0;
        const uint4* v4 = (const uint4*)(g_vC + ((long)(b * 512 + hh * 64)) * 296);
        for (int idx = t; idx < 2368; idx += 256) {
            int row = idx / 37, j = idx - row * 37;
            s4[SV_ / 4 + row * 39 + j] = v4[row * 37 + j];
        }
        for (int idx = t; idx < 512; idx += 256) {
            int row = idx >> 3, ww = idx & 7;
            smw[SV_ + row * 156 + 148 + ww] = 0;
        }
    }
    __syncthreads();

    // ---- QK^T ----
    float s[37][4];
#pragma unroll
    for (int nt = 0; nt < 37; nt++)
#pragma unroll
        for (int r = 0; r < 4; r++) s[nt][r] = 0.f;

    const int qrowbase = (w * 16 + qr) * 36 + qc;
#pragma unroll
    for (int kk = 0; kk < 4; kk++) {
        int qb = qrowbase + kk * 8;
        uint32_t a[4] = { smw[qb], smw[qb + 288], smw[qb + 4], smw[qb + 292] };
        int kbase = SK_ + qr * 36 + kk * 8 + qc;
#pragma unroll
        for (int nt = 0; nt < 37; nt++) {
            int kb = kbase + nt * 288;
            uint32_t bb[2] = { smw[kb], smw[kb + 4] };
            mma_f16(s[nt], a, bb);
        }
    }

    // ---- softmax ----
    float mx0 = -1e30f, mx1 = -1e30f;
#pragma unroll
    for (int nt = 0; nt < 36; nt++) {
        mx0 = fmaxf(mx0, fmaxf(s[nt][0], s[nt][1]));
        mx1 = fmaxf(mx1, fmaxf(s[nt][2], s[nt][3]));
    }
    if (qc == 0) { mx0 = fmaxf(mx0, s[36][0]); mx1 = fmaxf(mx1, s[36][2]); }
    mx0 = fmaxf(mx0, __shfl_xor_sync(0xffffffffu, mx0, 1));
    mx0 = fmaxf(mx0, __shfl_xor_sync(0xffffffffu, mx0, 2));
    mx1 = fmaxf(mx1, __shfl_xor_sync(0xffffffffu, mx1, 1));
    mx1 = fmaxf(mx1, __shfl_xor_sync(0xffffffffu, mx1, 2));

    float sum0 = 0.f, sum1 = 0.f;
#pragma unroll
    for (int nt = 0; nt < 36; nt++) {
        float e0 = __expf(s[nt][0] - mx0), e1 = __expf(s[nt][1] - mx0);
        float e2 = __expf(s[nt][2] - mx1), e3 = __expf(s[nt][3] - mx1);
        s[nt][0] = e0; s[nt][1] = e1; s[nt][2] = e2; s[nt][3] = e3;
        sum0 += e0 + e1; sum1 += e2 + e3;
    }
    {
        float e0 = (qc == 0) ? __expf(s[36][0] - mx0) : 0.f;
        float e2 = (qc == 0) ? __expf(s[36][2] - mx1) : 0.f;
        s[36][0] = e0; s[36][1] = 0.f; s[36][2] = e2; s[36][3] = 0.f;
        sum0 += e0; sum1 += e2;
    }
    sum0 += __shfl_xor_sync(0xffffffffu, sum0, 1);
    sum0 += __shfl_xor_sync(0xffffffffu, sum0, 2);
    sum1 += __shfl_xor_sync(0xffffffffu, sum1, 1);
    sum1 += __shfl_xor_sync(0xffffffffu, sum1, 2);
    float inv0 = 1.f / sum0, inv1 = 1.f / sum1;

    // normalize scores in place (P in fp32 registers)
#pragma unroll
    for (int nt = 0; nt < 37; nt++) {
        s[nt][0] *= inv0; s[nt][1] *= inv0;
        s[nt][2] *= inv1; s[nt][3] *= inv1;
    }

    // ---- AV: pack P fragments on the fly ----
    float o[8][4];
#pragma unroll
    for (int nt = 0; nt < 8; nt++)
#pragma unroll
        for (int r = 0; r < 4; r++) o[nt][r] = 0.f;

#pragma unroll
    for (int kc = 0; kc < 19; kc++) {
        const int t0 = 2 * kc, t1 = 2 * kc + 1;
        uint32_t a[4];
        a[0] = packh(s[t0][1], s[t0][0]);
        a[1] = packh(s[t0][3], s[t0][2]);
        if (t1 < 37) {
            a[2] = packh(s[t1][1], s[t1][0]);
            a[3] = packh(s[t1][3], s[t1][2]);
        } else {
            a[2] = 0u; a[3] = 0u;
        }
        int vb0 = SV_ + qr * 156 + kc * 8 + qc;
#pragma unroll
        for (int nt = 0; nt < 8; nt++) {
            int vb = vb0 + nt * 1248;
            uint32_t bb[2] = { smw[vb], smw[vb + 4] };
            mma_f16(o[nt], a, bb);
        }
    }

    // ---- stage + store (token-major fp16) ----
    __syncthreads();
    float* Osm = (float*)smw;   // [128][68]
#pragma unroll
    for (int nt = 0; nt < 8; nt++) {
        int col = nt * 8 + qc * 2;
        int r0 = (w * 16 + qr) * 68;
        Osm[r0 + col]              = o[nt][0];
        Osm[r0 + col + 1]          = o[nt][1];
        Osm[r0 + 8 * 68 + col]     = o[nt][2];
        Osm[r0 + 8 * 68 + col + 1] = o[nt][3];
    }
    __syncthreads();
    for (int idx = t; idx < 8192; idx += 256) {
        int tok = idx >> 6, dc = idx & 63;
        g_aoT[((long)(b * 4096 + n0 + tok)) * 512 + hh * 64 + dc] =
            __float2half_rn(Osm[tok * 68 + dc]);
    }
}

// ---------------------------------------------------------------------------
// launcher
// ---------------------------------------------------------------------------
extern "C" void kernel_launch(void* const* d_in, const int* in_sizes, int n_in,
                              void* d_out, int out_size)
{
    const float* sem  = (const float*)d_in[0];
    const float* spa  = (const float*)d_in[1];
    const float* x    = (const float*)d_in[2];
    const float* wq   = (const float*)d_in[3];
    const float* wdw  = (const float*)d_in[4];
    const float* lng  = (const float*)d_in[5];
    const float* lnb  = (const float*)d_in[6];
    const float* wpw  = (const float*)d_in[7];
    const float* wout = (const float*)d_in[8];
    float* out = (float*)d_out;

    const int GSM1 = 3 * 2 * 2 * 10240;   // 122880 (passes=1)
    const int GSM2 = 3 * 2 * 3 * 10240;   // 184320 (passes=2)
    cudaFuncSetAttribute(gemm_mma<1>, cudaFuncAttributeMaxDynamicSharedMemorySize, GSM1);
    cudaFuncSetAttribute(gemm_mma<2>, cudaFuncAttributeMaxDynamicSharedMemorySize, GSM2);
    cudaFuncSetAttribute(attn_kernel, cudaFuncAttributeMaxDynamicSharedMemorySize, ATTN_SMEM);

    prep_w<<<3072, 256>>>(wq, wpw, wout);
    transpose_split<<<dim3(128, 16, 8), dim3(32, 8)>>>(sem);
    dw_kernel<<<dim3(512, 8, 2), 128>>>(spa, x, wdw);
    ln_kernel<<<dim3(289, 8, 2), 512>>>(lng, lnb);

    // q (1-pass)
    gemm_mma<1><<<dim3(32, 4, 8), 256, GSM1>>>(0, 0, 0, nullptr, HWQ);
    // k + v merged (2-pass): z = b + 8*kv
    gemm_mma<2><<<dim3(3, 4, 16), 256, GSM2>>>(1, 1, 1, nullptr, NKV);
    attn_kernel<<<dim3(32, 64), 256, ATTN_SMEM>>>();
    // out (1-pass)
    gemm_mma<1><<<dim3(32, 4, 8), 256, GSM1>>>(3, 2, 3, out, HWQ);
}